// round 15
// baseline (speedup 1.0000x reference)
#include <cuda_runtime.h>
#include <cuda_fp16.h>
#include <cstdint>

#define N1 8192
#define N2 8192
#define D1 256
#define D2 128
#define NBLK (N2 / 64)    // 128 column-slabs (64-wide) of E

// ---------------------------------------------------------------------------
// Scratch (__device__ globals; allocation-free rule)
// ---------------------------------------------------------------------------
__device__ __half g_E[(size_t)N1 * N2];                // 128 MB: exp(S - pmax_slab)
__device__ float g_lse[N1];
__device__ float g_pmax[(size_t)NBLK * N1];            // 4 MB
__device__ float g_psum[(size_t)NBLK * N1];            // 4 MB
__device__ __half g_qh[N1 * D2], g_ql[N1 * D2];
__device__ __half g_x2h[N2 * D2], g_x2l[N2 * D2];
__device__ __half g_x2t[D2 * N2];
__device__ __half g_x1f[(size_t)N1 * D1];
__device__ float g_Wt[D1 * D2];

// ---------------------------------------------------------------------------
// Helpers
// ---------------------------------------------------------------------------
__device__ __forceinline__ uint32_t smem_u32(const void* p) {
    uint32_t a;
    asm("{ .reg .u64 t; cvta.to.shared.u64 t, %1; cvt.u32.u64 %0, t; }" : "=r"(a) : "l"(p));
    return a;
}
__device__ __forceinline__ void ldsm4(uint32_t r[4], uint32_t addr) {
    asm volatile("ldmatrix.sync.aligned.m8n8.x4.shared.b16 {%0,%1,%2,%3}, [%4];"
                 : "=r"(r[0]), "=r"(r[1]), "=r"(r[2]), "=r"(r[3]) : "r"(addr));
}
__device__ __forceinline__ void ldsm4t(uint32_t r[4], uint32_t addr) {
    asm volatile("ldmatrix.sync.aligned.m8n8.x4.trans.shared.b16 {%0,%1,%2,%3}, [%4];"
                 : "=r"(r[0]), "=r"(r[1]), "=r"(r[2]), "=r"(r[3]) : "r"(addr));
}
__device__ __forceinline__ void mma16816(float c[4], const uint32_t a[4], const uint32_t b[2]) {
    asm volatile("mma.sync.aligned.m16n8k16.row.col.f32.f16.f16.f32 "
                 "{%0,%1,%2,%3}, {%4,%5,%6,%7}, {%8,%9}, {%0,%1,%2,%3};"
                 : "+f"(c[0]), "+f"(c[1]), "+f"(c[2]), "+f"(c[3])
                 : "r"(a[0]), "r"(a[1]), "r"(a[2]), "r"(a[3]), "r"(b[0]), "r"(b[1]));
}
__device__ __forceinline__ void split_h(float v, __half& h, __half& l) {
    h = __float2half(v);
    l = __float2half(v - __half2float(h));
}
__device__ __forceinline__ void sts16(uint32_t addr, uint32_t a, uint32_t b,
                                      uint32_t c, uint32_t d) {
    asm volatile("st.shared.v4.b32 [%0], {%1,%2,%3,%4};"
                 :: "r"(addr), "r"(a), "r"(b), "r"(c), "r"(d) : "memory");
}
__device__ __forceinline__ uint32_t mulh2(uint32_t e, uint32_t s) {
    __half2 r = __hmul2(*(__half2*)&e, *(__half2*)&s);
    return *(uint32_t*)&r;
}

// ---------------------------------------------------------------------------
// Prep kernels
// ---------------------------------------------------------------------------
__global__ void transpose_w_kernel(const float* __restrict__ W1, float* __restrict__ Wt) {
    int idx = blockIdx.x * blockDim.x + threadIdx.x;
    if (idx < D1 * D2) {
        int n = idx / D1, k = idx % D1;
        Wt[k * D2 + n] = W1[idx];
    }
}

__global__ void q_gemm_kernel(const float* __restrict__ A, const float* __restrict__ B,
                              __half* __restrict__ Ch, __half* __restrict__ Cl,
                              const float* __restrict__ bias) {
    __shared__ float As[32][16];
    __shared__ float Bs[16][128];
    const int m0 = blockIdx.x * 32;
    const int tid = threadIdx.x;
    const int ty = tid >> 4, tx = tid & 15;
    float acc0[8] = {}, acc1[8] = {};

    for (int k0 = 0; k0 < D1; k0 += 16) {
        {
            int m = tid >> 3, k2 = (tid & 7) * 2;
            const float* p = A + (size_t)(m0 + m) * D1 + k0 + k2;
            As[m][k2] = p[0]; As[m][k2 + 1] = p[1];
        }
        #pragma unroll
        for (int c = 0; c < 2; c++) {
            int idx = c * 1024 + tid * 4;
            int k = idx >> 7, n = idx & 127;
            *(float4*)&Bs[k][n] = *(const float4*)(B + (size_t)(k0 + k) * 128 + n);
        }
        __syncthreads();
        #pragma unroll
        for (int k = 0; k < 16; k++) {
            float a0 = As[ty * 2][k], a1 = As[ty * 2 + 1][k];
            float4 b0 = *(const float4*)&Bs[k][tx * 8];
            float4 b1 = *(const float4*)&Bs[k][tx * 8 + 4];
            acc0[0] += a0 * b0.x; acc0[1] += a0 * b0.y; acc0[2] += a0 * b0.z; acc0[3] += a0 * b0.w;
            acc0[4] += a0 * b1.x; acc0[5] += a0 * b1.y; acc0[6] += a0 * b1.z; acc0[7] += a0 * b1.w;
            acc1[0] += a1 * b0.x; acc1[1] += a1 * b0.y; acc1[2] += a1 * b0.z; acc1[3] += a1 * b0.w;
            acc1[4] += a1 * b1.x; acc1[5] += a1 * b1.y; acc1[6] += a1 * b1.z; acc1[7] += a1 * b1.w;
        }
        __syncthreads();
    }
    int m = m0 + ty * 2;
    #pragma unroll
    for (int j = 0; j < 8; j++) {
        float bv = bias[tx * 8 + j];
        __half h, l;
        split_h(acc0[j] + bv, h, l);
        Ch[(size_t)m * 128 + tx * 8 + j] = h; Cl[(size_t)m * 128 + tx * 8 + j] = l;
        split_h(acc1[j] + bv, h, l);
        Ch[(size_t)(m + 1) * 128 + tx * 8 + j] = h; Cl[(size_t)(m + 1) * 128 + tx * 8 + j] = l;
    }
}

__global__ void split_kernel(const float* __restrict__ in, int n,
                             __half* __restrict__ oh, __half* __restrict__ ol) {
    int i = blockIdx.x * blockDim.x + threadIdx.x;
    if (i * 4 < n) {
        float4 v = *(const float4*)(in + (size_t)i * 4);
        __half h, l;
        size_t o = (size_t)i * 4;
        split_h(v.x, h, l); oh[o] = h;     ol[o] = l;
        split_h(v.y, h, l); oh[o + 1] = h; ol[o + 1] = l;
        split_h(v.z, h, l); oh[o + 2] = h; ol[o + 2] = l;
        split_h(v.w, h, l); oh[o + 3] = h; ol[o + 3] = l;
    }
}

__global__ void tofp16_kernel(const float* __restrict__ in, int n, __half* __restrict__ o) {
    int i = blockIdx.x * blockDim.x + threadIdx.x;
    if (i * 4 < n) {
        float4 v = *(const float4*)(in + (size_t)i * 4);
        __half2 a = __floats2half2_rn(v.x, v.y);
        __half2 b = __floats2half2_rn(v.z, v.w);
        *(__half2*)(o + (size_t)i * 4)     = a;
        *(__half2*)(o + (size_t)i * 4 + 2) = b;
    }
}

__global__ void transpose_h_kernel(const float* __restrict__ in, int R, int C,
                                   __half* __restrict__ o) {
    __shared__ float t[32][33];
    int c0 = blockIdx.x * 32, r0 = blockIdx.y * 32;
    for (int i = threadIdx.y; i < 32; i += 8)
        t[i][threadIdx.x] = in[(size_t)(r0 + i) * C + c0 + threadIdx.x];
    __syncthreads();
    for (int i = threadIdx.y; i < 32; i += 8)
        o[(size_t)(c0 + i) * R + r0 + threadIdx.x] = __float2half(t[threadIdx.x][i]);
}

// ---------------------------------------------------------------------------
// lse combine (128 slabs of 64 cols)
// ---------------------------------------------------------------------------
__global__ void lse_combine_kernel(const float* __restrict__ pmax,
                                   const float* __restrict__ psum,
                                   float* __restrict__ lse) {
    int row = blockIdx.x * 256 + threadIdx.x;
    float M = -1e30f;
    #pragma unroll 8
    for (int nb = 0; nb < NBLK; nb++)
        M = fmaxf(M, pmax[(size_t)nb * N1 + row]);
    float s = 0.0f;
    #pragma unroll 8
    for (int nb = 0; nb < NBLK; nb++)
        s += psum[(size_t)nb * N1 + row] * __expf(pmax[(size_t)nb * N1 + row] - M);
    lse[row] = M + __logf(s);
}

// ---------------------------------------------------------------------------
// S GEMM: BM=64, BN=64, split-fp16 3-MMA, OCCUPANCY 3 (64 KB smem).
// Warps: 2 in M (wid&1) x 4 in N (wid>>1); warp tile 32x16.
// Stage rows (128B each): Ah 0..63, Al 64..127, Bh 128..191, Bl 192..255.
// ---------------------------------------------------------------------------
static constexpr int S_STAGE = 256 * 128;   // 32 KB
static constexpr int SMEM_S  = 2 * S_STAGE; // 64 KB

__device__ __forceinline__ void s_load_stage(
    uint32_t base, int tid, int m0, int n0, int k0,
    const __half* Ah, const __half* Al, const __half* Bh, const __half* Bl) {
    #pragma unroll
    for (int it = 0; it < 8; it++) {
        int i = tid + it * 256;
        int c = i & 7, row = i >> 3;
        const __half* src;
        if (row < 64)        src = Ah + (size_t)(m0 + row) * D2 + k0 + c * 8;
        else if (row < 128)  src = Al + (size_t)(m0 + row - 64) * D2 + k0 + c * 8;
        else if (row < 192)  src = Bh + (size_t)(n0 + row - 128) * D2 + k0 + c * 8;
        else                 src = Bl + (size_t)(n0 + row - 192) * D2 + k0 + c * 8;
        uint32_t dst = base + row * 128 + ((c ^ (row & 7)) << 4);
        asm volatile("cp.async.cg.shared.global [%0], [%1], 16;" :: "r"(dst), "l"(src) : "memory");
    }
    asm volatile("cp.async.commit_group;" ::: "memory");
}

__global__ __launch_bounds__(256, 3) void gemm_s_kernel(
    const __half* __restrict__ Ah, const __half* __restrict__ Al,
    const __half* __restrict__ Bh, const __half* __restrict__ Bl,
    __half* __restrict__ E, float* __restrict__ pmax, float* __restrict__ psum) {
    extern __shared__ char smem[];
    const int tid = threadIdx.x, wid = tid >> 5, lane = tid & 31;
    const int m0 = blockIdx.y * 64, n0 = blockIdx.x * 64;
    const int wm0 = (wid & 1) * 32, wn0 = (wid >> 1) * 16;
    uint32_t sb = smem_u32(smem);

    const int a_r = lane & 15, a_k = lane >> 4;
    const int b_r = (lane & 7) + ((lane >> 4) << 3), b_k = (lane >> 3) & 1;

    float acc[2][2][4] = {};
    s_load_stage(sb, tid, m0, n0, 0, Ah, Al, Bh, Bl);
    s_load_stage(sb + S_STAGE, tid, m0, n0, 64, Ah, Al, Bh, Bl);

    for (int c = 0; c < 2; c++) {
        asm volatile("cp.async.wait_group %0;" :: "n"(0) : "memory");
        __syncthreads();
        const uint32_t st = sb + c * S_STAGE;
        #pragma unroll
        for (int ks = 0; ks < 4; ks++) {
            uint32_t afh[2][4], afl[2][4];
            #pragma unroll
            for (int mt = 0; mt < 2; mt++) {
                int r = wm0 + mt * 16 + a_r;
                int kc = ks * 2 + a_k;
                uint32_t col = (uint32_t)((kc ^ (r & 7)) << 4);
                ldsm4(afh[mt], st + r * 128 + col);
                ldsm4(afl[mt], st + (64 + r) * 128 + col);
            }
            uint32_t bfh[2][2], bfl[2][2];
            {
                int r = wn0 + b_r;
                int kc = ks * 2 + b_k;
                uint32_t col = (uint32_t)((kc ^ (r & 7)) << 4);
                uint32_t t[4];
                ldsm4(t, st + (128 + r) * 128 + col);
                bfh[0][0] = t[0]; bfh[0][1] = t[1];
                bfh[1][0] = t[2]; bfh[1][1] = t[3];
                ldsm4(t, st + (192 + r) * 128 + col);
                bfl[0][0] = t[0]; bfl[0][1] = t[1];
                bfl[1][0] = t[2]; bfl[1][1] = t[3];
            }
            #pragma unroll
            for (int mt = 0; mt < 2; mt++)
                #pragma unroll
                for (int nt = 0; nt < 2; nt++) {
                    mma16816(acc[mt][nt], afh[mt], bfh[nt]);
                    mma16816(acc[mt][nt], afh[mt], bfl[nt]);
                    mma16816(acc[mt][nt], afl[mt], bfh[nt]);
                }
        }
        __syncthreads();
    }

    // ---- epilogue: 64-slab row max -> E fp16 -> psum ----
    // warps g = wid&1 cover rows g*32..+32; 4 warps (wid>>1 = 0..3) share rows.
    float* pm = (float*)smem;      // [8][32]
    float* Ms = pm + 256;          // [64]
    float* ps = Ms + 64;           // [8][32]

    #pragma unroll
    for (int mt = 0; mt < 2; mt++)
        #pragma unroll
        for (int half = 0; half < 2; half++) {
            float mx = -1e30f;
            #pragma unroll
            for (int nt = 0; nt < 2; nt++)
                mx = fmaxf(mx, fmaxf(acc[mt][nt][2 * half], acc[mt][nt][2 * half + 1]));
            mx = fmaxf(mx, __shfl_xor_sync(~0u, mx, 1));
            mx = fmaxf(mx, __shfl_xor_sync(~0u, mx, 2));
            if ((lane & 3) == 0)
                pm[wid * 32 + mt * 16 + half * 8 + (lane >> 2)] = mx;
        }
    __syncthreads();
    if (tid < 64) {
        int g = tid >> 5, rlw = tid & 31;
        float m = pm[g * 32 + rlw];
        m = fmaxf(m, pm[(g + 2) * 32 + rlw]);
        m = fmaxf(m, pm[(g + 4) * 32 + rlw]);
        m = fmaxf(m, pm[(g + 6) * 32 + rlw]);
        Ms[tid] = m;
    }
    __syncthreads();

    #pragma unroll
    for (int mt = 0; mt < 2; mt++)
        #pragma unroll
        for (int half = 0; half < 2; half++) {
            int rl = wm0 + mt * 16 + half * 8 + (lane >> 2);
            float M = Ms[rl];
            float sm = 0.0f;
            #pragma unroll
            for (int nt = 0; nt < 2; nt++) {
                float e0 = __expf(acc[mt][nt][2 * half] - M);
                float e1 = __expf(acc[mt][nt][2 * half + 1] - M);
                sm += e0 + e1;
                __half2 h = __floats2half2_rn(e0, e1);
                *(__half2*)&E[(size_t)(m0 + rl) * N2 + n0 + wn0 + nt * 8 + (lane & 3) * 2] = h;
            }
            sm += __shfl_xor_sync(~0u, sm, 1);
            sm += __shfl_xor_sync(~0u, sm, 2);
            if ((lane & 3) == 0)
                ps[wid * 32 + mt * 16 + half * 8 + (lane >> 2)] = sm;
        }
    __syncthreads();
    if (tid < 64) {
        int g = tid >> 5, rlw = tid & 31;
        float s = ps[g * 32 + rlw] + ps[(g + 2) * 32 + rlw]
                + ps[(g + 4) * 32 + rlw] + ps[(g + 6) * 32 + rlw];
        pmax[(size_t)blockIdx.x * N1 + m0 + tid] = Ms[tid];
        psum[(size_t)blockIdx.x * N1 + m0 + tid] = s;
    }
}

// ---------------------------------------------------------------------------
// Fused consumer, OCCUPANCY 2: f2 (blocks 0..127) + f1 (128..255).
// smem: A 2x16KB @0, B 3x16KB @32KB = 80KB.
// ---------------------------------------------------------------------------
static constexpr int FB_OFF   = 32 * 1024;
static constexpr int FB_STAGE = 16 * 1024;
static constexpr int FUSED_SMEM = FB_OFF + 3 * FB_STAGE;   // 80 KB

__global__ __launch_bounds__(256, 2) void gemm_fused_kernel(
    const __half* __restrict__ E, const float* __restrict__ pmax,
    const float* __restrict__ lse,
    const __half* __restrict__ X2t, const __half* __restrict__ X1f,
    float* __restrict__ F1, float* __restrict__ F2) {
    extern __shared__ char smem[];
    uint32_t sb = smem_u32(smem);
    const int tid = threadIdx.x, wid = tid >> 5, lane = tid & 31;

    if (blockIdx.x < 128) {
        // ================= f2 tile: C[m0:+128][n0:+128] of attn^T @ x1 =====
        const int bid = blockIdx.x;
        const int m0 = (bid >> 1) * 128, n0 = (bid & 1) * 128;
        const int wm0 = (wid & 3) * 32, wn0 = (wid >> 2) * 64;
        const int lt = lane >> 3, li = lane & 7;
        constexpr int A_ST = 64 * 256;   // 16 KB

        float acc[2][8][4] = {};
        uint4 ereg[4];
        float sreg[4];
        const int nCh = N1 >> 6;   // 128

        auto ldgA = [&](int c) {
            #pragma unroll
            for (int it = 0; it < 4; it++) {
                int idx = tid + it * 256;
                int k = idx >> 4, cc = idx & 15;
                // E columns m0+cc*8 .. +8 all lie in 64-slab (m0>>6)+(cc>>3)
                ereg[it] = *(const uint4*)(E + (size_t)(c * 64 + k) * N2 + m0 + cc * 8);
                sreg[it] = __expf(pmax[(size_t)((m0 >> 6) + (cc >> 3)) * N1 + c * 64 + k]
                                  - __ldg(lse + c * 64 + k));
            }
        };
        auto stsA = [&](int buf) {
            uint32_t ab = sb + buf * A_ST;
            #pragma unroll
            for (int it = 0; it < 4; it++) {
                int idx = tid + it * 256;
                int k = idx >> 4, cc = idx & 15;
                __half2 s2h = __float2half2_rn(sreg[it]);
                uint32_t s2 = *(uint32_t*)&s2h;
                uint32_t off = k * 256 + ((cc ^ (k & 7)) << 4);
                sts16(ab + off, mulh2(ereg[it].x, s2), mulh2(ereg[it].y, s2),
                      mulh2(ereg[it].z, s2), mulh2(ereg[it].w, s2));
            }
        };
        auto ldB = [&](int c, int buf) {
            uint32_t bb = sb + FB_OFF + buf * FB_STAGE;
            #pragma unroll
            for (int it = 0; it < 4; it++) {
                int i = tid + it * 256;
                int k = i >> 4, cc = i & 15;
                const __half* src = X1f + (size_t)(c * 64 + k) * D1 + n0 + cc * 8;
                uint32_t dst = bb + k * 256 + ((cc ^ (k & 7)) << 4);
                asm volatile("cp.async.cg.shared.global [%0], [%1], 16;" :: "r"(dst), "l"(src) : "memory");
            }
            asm volatile("cp.async.commit_group;" ::: "memory");
        };

        ldgA(0); stsA(0);
        ldB(0, 0); ldB(1, 1);

        for (int c = 0; c < nCh; c++) {
            const bool more = (c + 1 < nCh);
            if (more) ldgA(c + 1);
            asm volatile("cp.async.wait_group 1;" ::: "memory");
            __syncthreads();
            if (c + 2 < nCh) ldB(c + 2, (c + 2) % 3);
            else asm volatile("cp.async.commit_group;" ::: "memory");

            const uint32_t ast = sb + (c & 1) * A_ST;
            const uint32_t bst = sb + FB_OFF + (c % 3) * FB_STAGE;
            #pragma unroll
            for (int ks = 0; ks < 4; ks++) {
                uint32_t afh[2][4];
                #pragma unroll
                for (int mt = 0; mt < 2; mt++) {
                    int mb = wm0 + mt * 16 + (lt & 1) * 8;
                    int k = ks * 16 + (lt >> 1) * 8 + li;
                    uint32_t addr = k * 256 + (((mb >> 3) ^ (k & 7)) << 4);
                    ldsm4t(afh[mt], ast + addr);
                }
                uint32_t bfh[8][2];
                #pragma unroll
                for (int nt = 0; nt < 8; nt += 2) {
                    int nb = wn0 + nt * 8 + (lt >> 1) * 8;
                    int k = ks * 16 + (lt & 1) * 8 + li;
                    uint32_t addr = k * 256 + (((nb >> 3) ^ (k & 7)) << 4);
                    uint32_t t[4];
                    ldsm4t(t, bst + addr);
                    bfh[nt][0] = t[0]; bfh[nt][1] = t[1];
                    bfh[nt + 1][0] = t[2]; bfh[nt + 1][1] = t[3];
                }
                #pragma unroll
                for (int mt = 0; mt < 2; mt++)
                    #pragma unroll
                    for (int nt = 0; nt < 8; nt++)
                        mma16816(acc[mt][nt], afh[mt], bfh[nt]);
            }
            if (more) stsA((c + 1) & 1);
        }

        #pragma unroll
        for (int mt = 0; mt < 2; mt++) {
            int row = m0 + wm0 + mt * 16 + (lane >> 2);
            #pragma unroll
            for (int nt = 0; nt < 8; nt++) {
                int col = n0 + wn0 + nt * 8 + (lane & 3) * 2;
                *(float2*)&F2[(size_t)row * D1 + col]       = make_float2(acc[mt][nt][0], acc[mt][nt][1]);
                *(float2*)&F2[(size_t)(row + 8) * D1 + col] = make_float2(acc[mt][nt][2], acc[mt][nt][3]);
            }
        }
    } else {
        // ================= f1 tile: C[m0:+64][0:128] of attn @ x2 ==========
        const int m0 = (blockIdx.x - 128) * 64;
        const int wm0 = (wid & 1) * 32, wn0 = (wid >> 1) * 32;
        const int a_r = lane & 15, a_k = lane >> 4;
        const int b_r = (lane & 7) + ((lane >> 4) << 3), b_k = (lane >> 3) & 1;
        constexpr int A_ST = 64 * 128;   // 8 KB

        float acc[2][4][4] = {};
        uint4 ereg[2];
        float sreg[2];
        const int nCh = N2 >> 6;   // 128

        float tl2[2];
        #pragma unroll
        for (int it = 0; it < 2; it++) tl2[it] = lse[m0 + ((tid + it * 256) >> 3)];

        auto ldgA = [&](int c) {
            // E columns c*64..+64 form exactly slab c
            #pragma unroll
            for (int it = 0; it < 2; it++) {
                int idx = tid + it * 256;
                int m = idx >> 3, kq = idx & 7;
                ereg[it] = *(const uint4*)(E + (size_t)(m0 + m) * N2 + c * 64 + kq * 8);
                sreg[it] = __expf(pmax[(size_t)c * N1 + m0 + m] - tl2[it]);
            }
        };
        auto stsA = [&](int buf) {
            uint32_t ab = sb + buf * A_ST;
            #pragma unroll
            for (int it = 0; it < 2; it++) {
                int idx = tid + it * 256;
                int m = idx >> 3, kq = idx & 7;
                __half2 s2h = __float2half2_rn(sreg[it]);
                uint32_t s2 = *(uint32_t*)&s2h;
                uint32_t off = m * 128 + ((kq ^ (m & 7)) << 4);
                sts16(ab + off, mulh2(ereg[it].x, s2), mulh2(ereg[it].y, s2),
                      mulh2(ereg[it].z, s2), mulh2(ereg[it].w, s2));
            }
        };
        auto ldB = [&](int c, int buf) {
            uint32_t bb = sb + FB_OFF + buf * FB_STAGE;
            #pragma unroll
            for (int it = 0; it < 4; it++) {
                int i = tid + it * 256;
                int n = i >> 3, cc = i & 7;
                const __half* src = X2t + (size_t)n * N2 + c * 64 + cc * 8;
                uint32_t dst = bb + n * 128 + ((cc ^ (n & 7)) << 4);
                asm volatile("cp.async.cg.shared.global [%0], [%1], 16;" :: "r"(dst), "l"(src) : "memory");
            }
            asm volatile("cp.async.commit_group;" ::: "memory");
        };

        ldgA(0); stsA(0);
        ldB(0, 0); ldB(1, 1);

        for (int c = 0; c < nCh; c++) {
            const bool more = (c + 1 < nCh);
            if (more) ldgA(c + 1);
            asm volatile("cp.async.wait_group 1;" ::: "memory");
            __syncthreads();
            if (c + 2 < nCh) ldB(c + 2, (c + 2) % 3);
            else asm volatile("cp.async.commit_group;" ::: "memory");

            const uint32_t ast = sb + (c & 1) * A_ST;
            const uint32_t bst = sb + FB_OFF + (c % 3) * FB_STAGE;
            #pragma unroll
            for (int ks = 0; ks < 4; ks++) {
                uint32_t afh[2][4];
                #pragma unroll
                for (int mt = 0; mt < 2; mt++) {
                    int r = wm0 + mt * 16 + a_r;
                    int kc = ks * 2 + a_k;
                    uint32_t col = (uint32_t)((kc ^ (r & 7)) << 4);
                    ldsm4(afh[mt], ast + r * 128 + col);
                }
                uint32_t bfh[4][2];
                #pragma unroll
                for (int nt = 0; nt < 4; nt += 2) {
                    int r = wn0 + nt * 8 + b_r;
                    int kc = ks * 2 + b_k;
                    uint32_t col = (uint32_t)((kc ^ (r & 7)) << 4);
                    uint32_t t[4];
                    ldsm4(t, bst + r * 128 + col);
                    bfh[nt][0] = t[0]; bfh[nt][1] = t[1];
                    bfh[nt + 1][0] = t[2]; bfh[nt + 1][1] = t[3];
                }
                #pragma unroll
                for (int mt = 0; mt < 2; mt++)
                    #pragma unroll
                    for (int nt = 0; nt < 4; nt++)
                        mma16816(acc[mt][nt], afh[mt], bfh[nt]);
            }
            if (more) stsA((c + 1) & 1);
        }

        #pragma unroll
        for (int mt = 0; mt < 2; mt++) {
            int row = m0 + wm0 + mt * 16 + (lane >> 2);
            #pragma unroll
            for (int nt = 0; nt < 4; nt++) {
                int col = wn0 + nt * 8 + (lane & 3) * 2;
                *(float2*)&F1[(size_t)row * D2 + col]       = make_float2(acc[mt][nt][0], acc[mt][nt][1]);
                *(float2*)&F1[(size_t)(row + 8) * D2 + col] = make_float2(acc[mt][nt][2], acc[mt][nt][3]);
            }
        }
    }
}

// ---------------------------------------------------------------------------
// Launch  (gemm_s at launch index 3 for the ncu capture slot)
// ---------------------------------------------------------------------------
extern "C" void kernel_launch(void* const* d_in, const int* in_sizes, int n_in,
                              void* d_out, int out_size) {
    const float* x1 = (const float*)d_in[0];   // [8192, 256]
    const float* x2 = (const float*)d_in[1];   // [8192, 128]
    const float* W1 = (const float*)d_in[2];   // [128, 256]
    const float* b1 = (const float*)d_in[3];   // [128]

    float* out = (float*)d_out;
    float* f1 = out;                          // [8192, 128]
    float* f2 = out + (size_t)N1 * D2;        // [8192, 256]

    float *wtp, *lsep, *pmaxp, *psump;
    __half *ep, *qh, *ql, *x2h, *x2l, *x2t, *x1f;
    cudaGetSymbolAddress((void**)&ep, g_E);
    cudaGetSymbolAddress((void**)&wtp, g_Wt);
    cudaGetSymbolAddress((void**)&lsep, g_lse);
    cudaGetSymbolAddress((void**)&pmaxp, g_pmax);
    cudaGetSymbolAddress((void**)&psump, g_psum);
    cudaGetSymbolAddress((void**)&qh, g_qh);
    cudaGetSymbolAddress((void**)&ql, g_ql);
    cudaGetSymbolAddress((void**)&x2h, g_x2h);
    cudaGetSymbolAddress((void**)&x2l, g_x2l);
    cudaGetSymbolAddress((void**)&x2t, g_x2t);
    cudaGetSymbolAddress((void**)&x1f, g_x1f);

    cudaFuncSetAttribute((const void*)gemm_s_kernel,
                         cudaFuncAttributeMaxDynamicSharedMemorySize, SMEM_S);
    cudaFuncSetAttribute((const void*)gemm_fused_kernel,
                         cudaFuncAttributeMaxDynamicSharedMemorySize, FUSED_SMEM);

    // prep needed by gemm_s only
    transpose_w_kernel<<<(D1 * D2 + 255) / 256, 256>>>(W1, wtp);              // 0
    q_gemm_kernel<<<N1 / 32, 256>>>(x1, wtp, qh, ql, b1);                     // 1
    split_kernel<<<(N2 * D2 / 4 + 255) / 256, 256>>>(x2, N2 * D2, x2h, x2l);  // 2
    // 3: the big S kernel (profiled slot), occupancy 3, BM=BN=64
    gemm_s_kernel<<<dim3(N2 / 64, N1 / 64), 256, SMEM_S>>>(
        qh, ql, x2h, x2l, ep, pmaxp, psump);
    // remaining prep for consumers
    transpose_h_kernel<<<dim3(D2 / 32, N2 / 32), dim3(32, 8)>>>(x2, N2, D2, x2t); // 4
    tofp16_kernel<<<(N1 * D1 / 4 + 255) / 256, 256>>>(x1, N1 * D1, x1f);          // 5
    lse_combine_kernel<<<N1 / 256, 256>>>(pmaxp, psump, lsep);                    // 6
    // 7: fused consumers (f2 blocks first)
    gemm_fused_kernel<<<256, 256, FUSED_SMEM>>>(ep, pmaxp, lsep, x2t, x1f, f1, f2);
}

// round 17
// speedup vs baseline: 1.0670x; 1.0670x over previous
#include <cuda_runtime.h>
#include <cuda_fp16.h>
#include <cstdint>

#define N1 8192
#define N2 8192
#define D1 256
#define D2 128
#define NBLK (N2 / 64)    // 128 column-slabs (64-wide) of E

// ---------------------------------------------------------------------------
// Scratch (__device__ globals; allocation-free rule)
// ---------------------------------------------------------------------------
__device__ __half g_E[(size_t)N1 * N2];                // 128 MB: exp(S - pmax_slab)
__device__ float g_lse[N1];
__device__ float g_pmax[(size_t)NBLK * N1];            // 4 MB
__device__ float g_psum[(size_t)NBLK * N1];            // 4 MB
__device__ float g_scale[(size_t)NBLK * N1];           // 4 MB: exp(pmax - lse)
__device__ __half g_qh[N1 * D2], g_ql[N1 * D2];
__device__ __half g_x2h[N2 * D2], g_x2l[N2 * D2];
__device__ __half g_x2t[D2 * N2];
__device__ __half g_x1f[(size_t)N1 * D1];
__device__ float g_Wt[D1 * D2];

// ---------------------------------------------------------------------------
// Helpers
// ---------------------------------------------------------------------------
__device__ __forceinline__ uint32_t smem_u32(const void* p) {
    uint32_t a;
    asm("{ .reg .u64 t; cvta.to.shared.u64 t, %1; cvt.u32.u64 %0, t; }" : "=r"(a) : "l"(p));
    return a;
}
__device__ __forceinline__ void ldsm4(uint32_t r[4], uint32_t addr) {
    asm volatile("ldmatrix.sync.aligned.m8n8.x4.shared.b16 {%0,%1,%2,%3}, [%4];"
                 : "=r"(r[0]), "=r"(r[1]), "=r"(r[2]), "=r"(r[3]) : "r"(addr));
}
__device__ __forceinline__ void ldsm4t(uint32_t r[4], uint32_t addr) {
    asm volatile("ldmatrix.sync.aligned.m8n8.x4.trans.shared.b16 {%0,%1,%2,%3}, [%4];"
                 : "=r"(r[0]), "=r"(r[1]), "=r"(r[2]), "=r"(r[3]) : "r"(addr));
}
__device__ __forceinline__ void mma16816(float c[4], const uint32_t a[4], const uint32_t b[2]) {
    asm volatile("mma.sync.aligned.m16n8k16.row.col.f32.f16.f16.f32 "
                 "{%0,%1,%2,%3}, {%4,%5,%6,%7}, {%8,%9}, {%0,%1,%2,%3};"
                 : "+f"(c[0]), "+f"(c[1]), "+f"(c[2]), "+f"(c[3])
                 : "r"(a[0]), "r"(a[1]), "r"(a[2]), "r"(a[3]), "r"(b[0]), "r"(b[1]));
}
__device__ __forceinline__ void split_h(float v, __half& h, __half& l) {
    h = __float2half(v);
    l = __float2half(v - __half2float(h));
}
__device__ __forceinline__ void sts16(uint32_t addr, uint32_t a, uint32_t b,
                                      uint32_t c, uint32_t d) {
    asm volatile("st.shared.v4.b32 [%0], {%1,%2,%3,%4};"
                 :: "r"(addr), "r"(a), "r"(b), "r"(c), "r"(d) : "memory");
}
__device__ __forceinline__ uint32_t mulh2(uint32_t e, uint32_t s) {
    __half2 r = __hmul2(*(__half2*)&e, *(__half2*)&s);
    return *(uint32_t*)&r;
}

// ---------------------------------------------------------------------------
// Prep kernels
// ---------------------------------------------------------------------------
__global__ void transpose_w_kernel(const float* __restrict__ W1, float* __restrict__ Wt) {
    int idx = blockIdx.x * blockDim.x + threadIdx.x;
    if (idx < D1 * D2) {
        int n = idx / D1, k = idx % D1;
        Wt[k * D2 + n] = W1[idx];
    }
}

__global__ void q_gemm_kernel(const float* __restrict__ A, const float* __restrict__ B,
                              __half* __restrict__ Ch, __half* __restrict__ Cl,
                              const float* __restrict__ bias) {
    __shared__ float As[32][16];
    __shared__ float Bs[16][128];
    const int m0 = blockIdx.x * 32;
    const int tid = threadIdx.x;
    const int ty = tid >> 4, tx = tid & 15;
    float acc0[8] = {}, acc1[8] = {};

    for (int k0 = 0; k0 < D1; k0 += 16) {
        {
            int m = tid >> 3, k2 = (tid & 7) * 2;
            const float* p = A + (size_t)(m0 + m) * D1 + k0 + k2;
            As[m][k2] = p[0]; As[m][k2 + 1] = p[1];
        }
        #pragma unroll
        for (int c = 0; c < 2; c++) {
            int idx = c * 1024 + tid * 4;
            int k = idx >> 7, n = idx & 127;
            *(float4*)&Bs[k][n] = *(const float4*)(B + (size_t)(k0 + k) * 128 + n);
        }
        __syncthreads();
        #pragma unroll
        for (int k = 0; k < 16; k++) {
            float a0 = As[ty * 2][k], a1 = As[ty * 2 + 1][k];
            float4 b0 = *(const float4*)&Bs[k][tx * 8];
            float4 b1 = *(const float4*)&Bs[k][tx * 8 + 4];
            acc0[0] += a0 * b0.x; acc0[1] += a0 * b0.y; acc0[2] += a0 * b0.z; acc0[3] += a0 * b0.w;
            acc0[4] += a0 * b1.x; acc0[5] += a0 * b1.y; acc0[6] += a0 * b1.z; acc0[7] += a0 * b1.w;
            acc1[0] += a1 * b0.x; acc1[1] += a1 * b0.y; acc1[2] += a1 * b0.z; acc1[3] += a1 * b0.w;
            acc1[4] += a1 * b1.x; acc1[5] += a1 * b1.y; acc1[6] += a1 * b1.z; acc1[7] += a1 * b1.w;
        }
        __syncthreads();
    }
    int m = m0 + ty * 2;
    #pragma unroll
    for (int j = 0; j < 8; j++) {
        float bv = bias[tx * 8 + j];
        __half h, l;
        split_h(acc0[j] + bv, h, l);
        Ch[(size_t)m * 128 + tx * 8 + j] = h; Cl[(size_t)m * 128 + tx * 8 + j] = l;
        split_h(acc1[j] + bv, h, l);
        Ch[(size_t)(m + 1) * 128 + tx * 8 + j] = h; Cl[(size_t)(m + 1) * 128 + tx * 8 + j] = l;
    }
}

__global__ void split_kernel(const float* __restrict__ in, int n,
                             __half* __restrict__ oh, __half* __restrict__ ol) {
    int i = blockIdx.x * blockDim.x + threadIdx.x;
    if (i * 4 < n) {
        float4 v = *(const float4*)(in + (size_t)i * 4);
        __half h, l;
        size_t o = (size_t)i * 4;
        split_h(v.x, h, l); oh[o] = h;     ol[o] = l;
        split_h(v.y, h, l); oh[o + 1] = h; ol[o + 1] = l;
        split_h(v.z, h, l); oh[o + 2] = h; ol[o + 2] = l;
        split_h(v.w, h, l); oh[o + 3] = h; ol[o + 3] = l;
    }
}

__global__ void tofp16_kernel(const float* __restrict__ in, int n, __half* __restrict__ o) {
    int i = blockIdx.x * blockDim.x + threadIdx.x;
    if (i * 4 < n) {
        float4 v = *(const float4*)(in + (size_t)i * 4);
        __half2 a = __floats2half2_rn(v.x, v.y);
        __half2 b = __floats2half2_rn(v.z, v.w);
        *(__half2*)(o + (size_t)i * 4)     = a;
        *(__half2*)(o + (size_t)i * 4 + 2) = b;
    }
}

__global__ void transpose_h_kernel(const float* __restrict__ in, int R, int C,
                                   __half* __restrict__ o) {
    __shared__ float t[32][33];
    int c0 = blockIdx.x * 32, r0 = blockIdx.y * 32;
    for (int i = threadIdx.y; i < 32; i += 8)
        t[i][threadIdx.x] = in[(size_t)(r0 + i) * C + c0 + threadIdx.x];
    __syncthreads();
    for (int i = threadIdx.y; i < 32; i += 8)
        o[(size_t)(c0 + i) * R + r0 + threadIdx.x] = __float2half(t[threadIdx.x][i]);
}

// ---------------------------------------------------------------------------
// lse combine + scale table over 128 slabs of 64 cols
// ---------------------------------------------------------------------------
__global__ void lse_combine_kernel(const float* __restrict__ pmax,
                                   const float* __restrict__ psum,
                                   float* __restrict__ lse,
                                   float* __restrict__ scale) {
    int row = blockIdx.x * 256 + threadIdx.x;
    float M = -1e30f;
    #pragma unroll 8
    for (int nb = 0; nb < NBLK; nb++)
        M = fmaxf(M, pmax[(size_t)nb * N1 + row]);
    float s = 0.0f;
    #pragma unroll 8
    for (int nb = 0; nb < NBLK; nb++)
        s += psum[(size_t)nb * N1 + row] * __expf(pmax[(size_t)nb * N1 + row] - M);
    float L = M + __logf(s);
    lse[row] = L;
    #pragma unroll 8
    for (int nb = 0; nb < NBLK; nb++)
        scale[(size_t)nb * N1 + row] = __expf(pmax[(size_t)nb * N1 + row] - L);
}

// ---------------------------------------------------------------------------
// S GEMM (R13 config): BM=128, BN=64, split-fp16 3-MMA, OCCUPANCY 2 (96 KB).
// grid.x = N2/64 = 128 slabs of 64 columns; slab index = blockIdx.x.
// Stage rows (128B each): Ah 0..127, Al 128..255, Bh 256..319, Bl 320..383.
// ---------------------------------------------------------------------------
static constexpr int S_STAGE = (2 * 128 + 2 * 64) * 128;  // 48 KB
static constexpr int SMEM_S  = 2 * S_STAGE;               // 96 KB

__device__ __forceinline__ void s_load_stage(
    uint32_t base, int tid, int m0, int n0, int k0,
    const __half* Ah, const __half* Al, const __half* Bh, const __half* Bl) {
    #pragma unroll
    for (int it = 0; it < 12; it++) {
        int i = tid + it * 256;
        int c = i & 7, row = i >> 3;
        const __half* src;
        if (row < 128)       src = Ah + (size_t)(m0 + row) * D2 + k0 + c * 8;
        else if (row < 256)  src = Al + (size_t)(m0 + row - 128) * D2 + k0 + c * 8;
        else if (row < 320)  src = Bh + (size_t)(n0 + row - 256) * D2 + k0 + c * 8;
        else                 src = Bl + (size_t)(n0 + row - 320) * D2 + k0 + c * 8;
        uint32_t dst = base + row * 128 + ((c ^ (row & 7)) << 4);
        asm volatile("cp.async.cg.shared.global [%0], [%1], 16;" :: "r"(dst), "l"(src) : "memory");
    }
    asm volatile("cp.async.commit_group;" ::: "memory");
}

__global__ __launch_bounds__(256, 2) void gemm_s_kernel(
    const __half* __restrict__ Ah, const __half* __restrict__ Al,
    const __half* __restrict__ Bh, const __half* __restrict__ Bl,
    __half* __restrict__ E, float* __restrict__ pmax, float* __restrict__ psum) {
    extern __shared__ char smem[];
    const int tid = threadIdx.x, wid = tid >> 5, lane = tid & 31;
    const int m0 = blockIdx.y * 128, n0 = blockIdx.x * 64;
    const int wm0 = (wid & 3) * 32, wn0 = (wid >> 2) * 32;
    uint32_t sb = smem_u32(smem);

    const int a_r = lane & 15, a_k = lane >> 4;
    const int b_r = (lane & 7) + ((lane >> 4) << 3), b_k = (lane >> 3) & 1;

    float acc[2][4][4] = {};
    s_load_stage(sb, tid, m0, n0, 0, Ah, Al, Bh, Bl);
    s_load_stage(sb + S_STAGE, tid, m0, n0, 64, Ah, Al, Bh, Bl);

    for (int c = 0; c < 2; c++) {
        asm volatile("cp.async.wait_group %0;" :: "n"(0) : "memory");
        __syncthreads();
        const uint32_t st = sb + c * S_STAGE;
        #pragma unroll
        for (int ks = 0; ks < 4; ks++) {
            uint32_t afh[2][4], afl[2][4];
            #pragma unroll
            for (int mt = 0; mt < 2; mt++) {
                int r = wm0 + mt * 16 + a_r;
                int kc = ks * 2 + a_k;
                uint32_t col = (uint32_t)((kc ^ (r & 7)) << 4);
                ldsm4(afh[mt], st + r * 128 + col);
                ldsm4(afl[mt], st + (128 + r) * 128 + col);
            }
            uint32_t bfh[4][2], bfl[4][2];
            #pragma unroll
            for (int nt = 0; nt < 4; nt += 2) {
                int r = wn0 + nt * 8 + b_r;
                int kc = ks * 2 + b_k;
                uint32_t col = (uint32_t)((kc ^ (r & 7)) << 4);
                uint32_t t[4];
                ldsm4(t, st + (256 + r) * 128 + col);
                bfh[nt][0] = t[0]; bfh[nt][1] = t[1];
                bfh[nt + 1][0] = t[2]; bfh[nt + 1][1] = t[3];
                ldsm4(t, st + (320 + r) * 128 + col);
                bfl[nt][0] = t[0]; bfl[nt][1] = t[1];
                bfl[nt + 1][0] = t[2]; bfl[nt + 1][1] = t[3];
            }
            #pragma unroll
            for (int mt = 0; mt < 2; mt++)
                #pragma unroll
                for (int nt = 0; nt < 4; nt++) {
                    mma16816(acc[mt][nt], afh[mt], bfh[nt]);
                    mma16816(acc[mt][nt], afh[mt], bfl[nt]);
                    mma16816(acc[mt][nt], afl[mt], bfh[nt]);
                }
        }
        __syncthreads();
    }

    // ---- epilogue: 64-col slab row max -> E fp16 -> psum ----
    float* pm = (float*)smem;      // [8][32]
    float* Ms = pm + 256;          // [128]
    float* ps = Ms + 128;          // [8][32]

    #pragma unroll
    for (int mt = 0; mt < 2; mt++)
        #pragma unroll
        for (int half = 0; half < 2; half++) {
            float mx = -1e30f;
            #pragma unroll
            for (int nt = 0; nt < 4; nt++)
                mx = fmaxf(mx, fmaxf(acc[mt][nt][2 * half], acc[mt][nt][2 * half + 1]));
            mx = fmaxf(mx, __shfl_xor_sync(~0u, mx, 1));
            mx = fmaxf(mx, __shfl_xor_sync(~0u, mx, 2));
            if ((lane & 3) == 0)
                pm[wid * 32 + mt * 16 + half * 8 + (lane >> 2)] = mx;
        }
    __syncthreads();
    if (tid < 128) {
        int a = tid >> 5, rlw = tid & 31;
        Ms[tid] = fmaxf(pm[a * 32 + rlw], pm[(a + 4) * 32 + rlw]);
    }
    __syncthreads();

    #pragma unroll
    for (int mt = 0; mt < 2; mt++)
        #pragma unroll
        for (int half = 0; half < 2; half++) {
            int rl = wm0 + mt * 16 + half * 8 + (lane >> 2);
            float M = Ms[rl];
            float sm = 0.0f;
            #pragma unroll
            for (int nt = 0; nt < 4; nt++) {
                float e0 = __expf(acc[mt][nt][2 * half] - M);
                float e1 = __expf(acc[mt][nt][2 * half + 1] - M);
                sm += e0 + e1;
                __half2 h = __floats2half2_rn(e0, e1);
                *(__half2*)&E[(size_t)(m0 + rl) * N2 + n0 + wn0 + nt * 8 + (lane & 3) * 2] = h;
            }
            sm += __shfl_xor_sync(~0u, sm, 1);
            sm += __shfl_xor_sync(~0u, sm, 2);
            if ((lane & 3) == 0)
                ps[wid * 32 + mt * 16 + half * 8 + (lane >> 2)] = sm;
        }
    __syncthreads();
    if (tid < 128) {
        int a = tid >> 5, rlw = tid & 31;
        pmax[(size_t)blockIdx.x * N1 + m0 + tid] = Ms[tid];
        psum[(size_t)blockIdx.x * N1 + m0 + tid] = ps[a * 32 + rlw] + ps[(a + 4) * 32 + rlw];
    }
}

// ---------------------------------------------------------------------------
// Fused consumer, OCCUPANCY 2: f2 (blocks 0..127) + f1 (128..255).
// Uses precomputed g_scale (128 slabs of 64 cols).
// smem: A 2x16KB @0, B 3x16KB @32KB = 80KB.
// ---------------------------------------------------------------------------
static constexpr int FB_OFF   = 32 * 1024;
static constexpr int FB_STAGE = 16 * 1024;
static constexpr int FUSED_SMEM = FB_OFF + 3 * FB_STAGE;   // 80 KB

__global__ __launch_bounds__(256, 2) void gemm_fused_kernel(
    const __half* __restrict__ E, const float* __restrict__ scale,
    const __half* __restrict__ X2t, const __half* __restrict__ X1f,
    float* __restrict__ F1, float* __restrict__ F2) {
    extern __shared__ char smem[];
    uint32_t sb = smem_u32(smem);
    const int tid = threadIdx.x, wid = tid >> 5, lane = tid & 31;

    if (blockIdx.x < 128) {
        // ================= f2 tile: C[m0:+128][n0:+128] of attn^T @ x1 =====
        const int bid = blockIdx.x;
        const int m0 = (bid >> 1) * 128, n0 = (bid & 1) * 128;
        const int wm0 = (wid & 3) * 32, wn0 = (wid >> 2) * 64;
        const int lt = lane >> 3, li = lane & 7;
        constexpr int A_ST = 64 * 256;   // 16 KB

        float acc[2][8][4] = {};
        uint4 ereg[4];
        float sreg[4];
        const int nCh = N1 >> 6;   // 128

        auto ldgA = [&](int c) {
            #pragma unroll
            for (int it = 0; it < 4; it++) {
                int idx = tid + it * 256;
                int k = idx >> 4, cc = idx & 15;
                // E columns m0+cc*8..+8 lie in 64-col slab (m0>>6)+(cc>>3)
                ereg[it] = *(const uint4*)(E + (size_t)(c * 64 + k) * N2 + m0 + cc * 8);
                sreg[it] = __ldg(scale + (size_t)((m0 >> 6) + (cc >> 3)) * N1 + c * 64 + k);
            }
        };
        auto stsA = [&](int buf) {
            uint32_t ab = sb + buf * A_ST;
            #pragma unroll
            for (int it = 0; it < 4; it++) {
                int idx = tid + it * 256;
                int k = idx >> 4, cc = idx & 15;
                __half2 s2h = __float2half2_rn(sreg[it]);
                uint32_t s2 = *(uint32_t*)&s2h;
                uint32_t off = k * 256 + ((cc ^ (k & 7)) << 4);
                sts16(ab + off, mulh2(ereg[it].x, s2), mulh2(ereg[it].y, s2),
                      mulh2(ereg[it].z, s2), mulh2(ereg[it].w, s2));
            }
        };
        auto ldB = [&](int c, int buf) {
            uint32_t bb = sb + FB_OFF + buf * FB_STAGE;
            #pragma unroll
            for (int it = 0; it < 4; it++) {
                int i = tid + it * 256;
                int k = i >> 4, cc = i & 15;
                const __half* src = X1f + (size_t)(c * 64 + k) * D1 + n0 + cc * 8;
                uint32_t dst = bb + k * 256 + ((cc ^ (k & 7)) << 4);
                asm volatile("cp.async.cg.shared.global [%0], [%1], 16;" :: "r"(dst), "l"(src) : "memory");
            }
            asm volatile("cp.async.commit_group;" ::: "memory");
        };

        ldgA(0); stsA(0);
        ldB(0, 0); ldB(1, 1);

        for (int c = 0; c < nCh; c++) {
            const bool more = (c + 1 < nCh);
            if (more) ldgA(c + 1);
            asm volatile("cp.async.wait_group 1;" ::: "memory");
            __syncthreads();
            if (c + 2 < nCh) ldB(c + 2, (c + 2) % 3);
            else asm volatile("cp.async.commit_group;" ::: "memory");

            const uint32_t ast = sb + (c & 1) * A_ST;
            const uint32_t bst = sb + FB_OFF + (c % 3) * FB_STAGE;
            #pragma unroll
            for (int ks = 0; ks < 4; ks++) {
                uint32_t afh[2][4];
                #pragma unroll
                for (int mt = 0; mt < 2; mt++) {
                    int mb = wm0 + mt * 16 + (lt & 1) * 8;
                    int k = ks * 16 + (lt >> 1) * 8 + li;
                    uint32_t addr = k * 256 + (((mb >> 3) ^ (k & 7)) << 4);
                    ldsm4t(afh[mt], ast + addr);
                }
                uint32_t bfh[8][2];
                #pragma unroll
                for (int nt = 0; nt < 8; nt += 2) {
                    int nb = wn0 + nt * 8 + (lt >> 1) * 8;
                    int k = ks * 16 + (lt & 1) * 8 + li;
                    uint32_t addr = k * 256 + (((nb >> 3) ^ (k & 7)) << 4);
                    uint32_t t[4];
                    ldsm4t(t, bst + addr);
                    bfh[nt][0] = t[0]; bfh[nt][1] = t[1];
                    bfh[nt + 1][0] = t[2]; bfh[nt + 1][1] = t[3];
                }
                #pragma unroll
                for (int mt = 0; mt < 2; mt++)
                    #pragma unroll
                    for (int nt = 0; nt < 8; nt++)
                        mma16816(acc[mt][nt], afh[mt], bfh[nt]);
            }
            if (more) stsA((c + 1) & 1);
        }

        #pragma unroll
        for (int mt = 0; mt < 2; mt++) {
            int row = m0 + wm0 + mt * 16 + (lane >> 2);
            #pragma unroll
            for (int nt = 0; nt < 8; nt++) {
                int col = n0 + wn0 + nt * 8 + (lane & 3) * 2;
                *(float2*)&F2[(size_t)row * D1 + col]       = make_float2(acc[mt][nt][0], acc[mt][nt][1]);
                *(float2*)&F2[(size_t)(row + 8) * D1 + col] = make_float2(acc[mt][nt][2], acc[mt][nt][3]);
            }
        }
    } else {
        // ================= f1 tile: C[m0:+64][0:128] of attn @ x2 ==========
        const int m0 = (blockIdx.x - 128) * 64;
        const int wm0 = (wid & 1) * 32, wn0 = (wid >> 1) * 32;
        const int a_r = lane & 15, a_k = lane >> 4;
        const int b_r = (lane & 7) + ((lane >> 4) << 3), b_k = (lane >> 3) & 1;
        constexpr int A_ST = 64 * 128;   // 8 KB

        float acc[2][4][4] = {};
        uint4 ereg[2];
        float sreg[2];
        const int nCh = N2 >> 6;   // 128

        auto ldgA = [&](int c) {
            // E columns c*64..+64 form exactly 64-col slab c
            #pragma unroll
            for (int it = 0; it < 2; it++) {
                int idx = tid + it * 256;
                int m = idx >> 3, kq = idx & 7;
                ereg[it] = *(const uint4*)(E + (size_t)(m0 + m) * N2 + c * 64 + kq * 8);
                sreg[it] = __ldg(scale + (size_t)c * N1 + m0 + m);
            }
        };
        auto stsA = [&](int buf) {
            uint32_t ab = sb + buf * A_ST;
            #pragma unroll
            for (int it = 0; it < 2; it++) {
                int idx = tid + it * 256;
                int m = idx >> 3, kq = idx & 7;
                __half2 s2h = __float2half2_rn(sreg[it]);
                uint32_t s2 = *(uint32_t*)&s2h;
                uint32_t off = m * 128 + ((kq ^ (m & 7)) << 4);
                sts16(ab + off, mulh2(ereg[it].x, s2), mulh2(ereg[it].y, s2),
                      mulh2(ereg[it].z, s2), mulh2(ereg[it].w, s2));
            }
        };
        auto ldB = [&](int c, int buf) {
            uint32_t bb = sb + FB_OFF + buf * FB_STAGE;
            #pragma unroll
            for (int it = 0; it < 4; it++) {
                int i = tid + it * 256;
                int n = i >> 3, cc = i & 7;
                const __half* src = X2t + (size_t)n * N2 + c * 64 + cc * 8;
                uint32_t dst = bb + n * 128 + ((cc ^ (n & 7)) << 4);
                asm volatile("cp.async.cg.shared.global [%0], [%1], 16;" :: "r"(dst), "l"(src) : "memory");
            }
            asm volatile("cp.async.commit_group;" ::: "memory");
        };

        ldgA(0); stsA(0);
        ldB(0, 0); ldB(1, 1);

        for (int c = 0; c < nCh; c++) {
            const bool more = (c + 1 < nCh);
            if (more) ldgA(c + 1);
            asm volatile("cp.async.wait_group 1;" ::: "memory");
            __syncthreads();
            if (c + 2 < nCh) ldB(c + 2, (c + 2) % 3);
            else asm volatile("cp.async.commit_group;" ::: "memory");

            const uint32_t ast = sb + (c & 1) * A_ST;
            const uint32_t bst = sb + FB_OFF + (c % 3) * FB_STAGE;
            #pragma unroll
            for (int ks = 0; ks < 4; ks++) {
                uint32_t afh[2][4];
                #pragma unroll
                for (int mt = 0; mt < 2; mt++) {
                    int r = wm0 + mt * 16 + a_r;
                    int kc = ks * 2 + a_k;
                    uint32_t col = (uint32_t)((kc ^ (r & 7)) << 4);
                    ldsm4(afh[mt], ast + r * 128 + col);
                }
                uint32_t bfh[4][2];
                #pragma unroll
                for (int nt = 0; nt < 4; nt += 2) {
                    int r = wn0 + nt * 8 + b_r;
                    int kc = ks * 2 + b_k;
                    uint32_t col = (uint32_t)((kc ^ (r & 7)) << 4);
                    uint32_t t[4];
                    ldsm4(t, bst + r * 128 + col);
                    bfh[nt][0] = t[0]; bfh[nt][1] = t[1];
                    bfh[nt + 1][0] = t[2]; bfh[nt + 1][1] = t[3];
                }
                #pragma unroll
                for (int mt = 0; mt < 2; mt++)
                    #pragma unroll
                    for (int nt = 0; nt < 4; nt++)
                        mma16816(acc[mt][nt], afh[mt], bfh[nt]);
            }
            if (more) stsA((c + 1) & 1);
        }

        #pragma unroll
        for (int mt = 0; mt < 2; mt++) {
            int row = m0 + wm0 + mt * 16 + (lane >> 2);
            #pragma unroll
            for (int nt = 0; nt < 4; nt++) {
                int col = wn0 + nt * 8 + (lane & 3) * 2;
                *(float2*)&F1[(size_t)row * D2 + col]       = make_float2(acc[mt][nt][0], acc[mt][nt][1]);
                *(float2*)&F1[(size_t)(row + 8) * D2 + col] = make_float2(acc[mt][nt][2], acc[mt][nt][3]);
            }
        }
    }
}

// ---------------------------------------------------------------------------
// Launch  (gemm_s at launch index 3 for the ncu capture slot)
// ---------------------------------------------------------------------------
extern "C" void kernel_launch(void* const* d_in, const int* in_sizes, int n_in,
                              void* d_out, int out_size) {
    const float* x1 = (const float*)d_in[0];   // [8192, 256]
    const float* x2 = (const float*)d_in[1];   // [8192, 128]
    const float* W1 = (const float*)d_in[2];   // [128, 256]
    const float* b1 = (const float*)d_in[3];   // [128]

    float* out = (float*)d_out;
    float* f1 = out;                          // [8192, 128]
    float* f2 = out + (size_t)N1 * D2;        // [8192, 256]

    float *wtp, *lsep, *pmaxp, *psump, *scalep;
    __half *ep, *qh, *ql, *x2h, *x2l, *x2t, *x1f;
    cudaGetSymbolAddress((void**)&ep, g_E);
    cudaGetSymbolAddress((void**)&wtp, g_Wt);
    cudaGetSymbolAddress((void**)&lsep, g_lse);
    cudaGetSymbolAddress((void**)&pmaxp, g_pmax);
    cudaGetSymbolAddress((void**)&psump, g_psum);
    cudaGetSymbolAddress((void**)&scalep, g_scale);
    cudaGetSymbolAddress((void**)&qh, g_qh);
    cudaGetSymbolAddress((void**)&ql, g_ql);
    cudaGetSymbolAddress((void**)&x2h, g_x2h);
    cudaGetSymbolAddress((void**)&x2l, g_x2l);
    cudaGetSymbolAddress((void**)&x2t, g_x2t);
    cudaGetSymbolAddress((void**)&x1f, g_x1f);

    cudaFuncSetAttribute((const void*)gemm_s_kernel,
                         cudaFuncAttributeMaxDynamicSharedMemorySize, SMEM_S);
    cudaFuncSetAttribute((const void*)gemm_fused_kernel,
                         cudaFuncAttributeMaxDynamicSharedMemorySize, FUSED_SMEM);

    // prep needed by gemm_s only
    transpose_w_kernel<<<(D1 * D2 + 255) / 256, 256>>>(W1, wtp);              // 0
    q_gemm_kernel<<<N1 / 32, 256>>>(x1, wtp, qh, ql, b1);                     // 1
    split_kernel<<<(N2 * D2 / 4 + 255) / 256, 256>>>(x2, N2 * D2, x2h, x2l);  // 2
    // 3: the big S kernel (profiled slot), R13 config: BM=128, BN=64, occ 2
    gemm_s_kernel<<<dim3(N2 / 64, N1 / 128), 256, SMEM_S>>>(
        qh, ql, x2h, x2l, ep, pmaxp, psump);
    // remaining prep for consumers
    transpose_h_kernel<<<dim3(D2 / 32, N2 / 32), dim3(32, 8)>>>(x2, N2, D2, x2t); // 4
    tofp16_kernel<<<(N1 * D1 / 4 + 255) / 256, 256>>>(x1, N1 * D1, x1f);          // 5
    lse_combine_kernel<<<N1 / 256, 256>>>(pmaxp, psump, lsep, scalep);            // 6
    // 7: fused consumers (f2 blocks first)
    gemm_fused_kernel<<<256, 256, FUSED_SMEM>>>(ep, scalep, x2t, x1f, f1, f2);
}